// round 14
// baseline (speedup 1.0000x reference)
#include <cuda_runtime.h>
#include <cuda_fp16.h>
#include <cstdint>

#define NSTEPS 32

// ---- smem layout (bytes) ----
#define OFF_W1T 0        // 4 nets x 64 n x 72 halves (pitch 144B) = 36864
#define OFF_A   36864    // 8 warps x 2 nets x 16 rows x 128B (XOR-swizzled) = 32768
#define OFF_W04 69632    // float4[256]  (w.x, w.y, cb, w.w) with cb = w.z*rf + b0
#define OFF_BW  73728    // float2[256] (b1, w2)
#define OFF_B2  75776    // float[4]
#define OFF_RED 75792    // float[8]
#define SMEM_BYTES 75824

#define A_WARP_B   4096
#define A_NET_B    2048
#define A_PITCH_B  128
#define B_NET_B    9216
#define B_ROW_B    144

__device__ float g_partial[256];

__device__ __forceinline__ uint32_t smem_u32(const void* p) {
    uint32_t a;
    asm("{ .reg .u64 t; cvta.to.shared.u64 t, %1; cvt.u32.u64 %0, t; }" : "=r"(a) : "l"(p));
    return a;
}
__device__ __forceinline__ float tanh_fast(float x) {
    float y;
    asm("tanh.approx.f32 %0, %1;" : "=f"(y) : "f"(x));
    return y;
}
__device__ __forceinline__ void ldsm_x4(uint32_t& r0, uint32_t& r1, uint32_t& r2, uint32_t& r3,
                                        uint32_t addr) {
    asm volatile("ldmatrix.sync.aligned.m8n8.x4.shared.b16 {%0,%1,%2,%3}, [%4];"
        : "=r"(r0), "=r"(r1), "=r"(r2), "=r"(r3) : "r"(addr));
}
__device__ __forceinline__ void mma16816_v(float& c0, float& c1, float& c2, float& c3,
                                           uint32_t a0, uint32_t a1, uint32_t a2, uint32_t a3,
                                           uint32_t b0, uint32_t b1) {
    asm volatile(
        "mma.sync.aligned.m16n8k16.row.col.f32.f16.f16.f32 "
        "{%0,%1,%2,%3},{%4,%5,%6,%7},{%8,%9},{%0,%1,%2,%3};"
        : "+f"(c0), "+f"(c1), "+f"(c2), "+f"(c3)
        : "r"(a0), "r"(a1), "r"(a2), "r"(a3), "r"(b0), "r"(b1));
}

// One phase, fully warp-local. Warp owns 16 rows; lane l = (row l&15, dup l>>4).
__device__ __forceinline__ void run_phase(
    int nb, float S, float V, float tcol,
    char* ab, uint32_t smb, int warp, int lane, int rl, int dup,
    float& fA, float& fB)
{
    const float4* w04 = (const float4*)(ab + OFF_W04);
    const float2* bw  = (const float2*)(ab + OFF_BW);
    const float*  b2s = (const float*)(ab + OFF_B2);

    const int g   = lane >> 2;
    const int tig = lane & 3;
    const int jbase = dup * 32;
    const int rsw = rl & 7;

    __syncwarp();   // WAR: prior phase's ldmatrix reads of A complete before overwrite

    // ---- layer 0: (wS, wV, cb, wT); 3 FMA + f32 tanh per unit ----
    {
        char* Abase = ab + OFF_A + warp * A_WARP_B + rl * A_PITCH_B;
        #pragma unroll
        for (int nl = 0; nl < 2; ++nl) {
            const int net = nb + nl;
            const float4* wp = w04 + net * 64 + jbase;
            char* An = Abase + nl * A_NET_B;
            #pragma unroll
            for (int jj = 0; jj < 32; jj += 4) {
                float4 w0 = wp[jj], w1 = wp[jj + 1], w2 = wp[jj + 2], w3 = wp[jj + 3];
                float p0 = fmaf(w0.x, S, fmaf(w0.y, V, fmaf(w0.w, tcol, w0.z)));
                float p1 = fmaf(w1.x, S, fmaf(w1.y, V, fmaf(w1.w, tcol, w1.z)));
                float p2 = fmaf(w2.x, S, fmaf(w2.y, V, fmaf(w2.w, tcol, w2.z)));
                float p3 = fmaf(w3.x, S, fmaf(w3.y, V, fmaf(w3.w, tcol, w3.z)));
                __half2 ha = __floats2half2_rn(tanh_fast(p0), tanh_fast(p1));
                __half2 hb = __floats2half2_rn(tanh_fast(p2), tanh_fast(p3));
                uint2 pk;
                pk.x = *(const uint32_t*)&ha;
                pk.y = *(const uint32_t*)&hb;
                const int unit = (dup * 4 + (jj >> 3)) ^ rsw;
                *(uint2*)(An + unit * 16 + ((jj >> 2) & 1) * 8) = pk;
            }
        }
    }
    __syncwarp();

    // ---- layer 1 + epilogue, per net ----
    const int arow = (lane & 7) + ((lane >> 3) & 1) * 8;
    const int akh  = (lane >> 4) & 1;
    const int asw  = arow & 7;
    const uint32_t a_lane = smb + OFF_A + warp * A_WARP_B + arow * A_PITCH_B;
    const uint32_t b_lane = smb + OFF_W1T + (lane & 7) * B_ROW_B + (lane >> 3) * 16;

    float pv0[2], pv1[2];

    #pragma unroll
    for (int nl = 0; nl < 2; ++nl) {
        const int net = nb + nl;

        uint32_t afr[4][4];
        {
            const uint32_t abase = a_lane + nl * A_NET_B;
            #pragma unroll
            for (int kt = 0; kt < 4; ++kt) {
                const int unit = (kt * 2 + akh) ^ asw;
                ldsm_x4(afr[kt][0], afr[kt][1], afr[kt][2], afr[kt][3],
                        abase + unit * 16);
            }
        }

        float partial0 = 0.f, partial1 = 0.f;
        const uint32_t bb = b_lane + net * B_NET_B;

        #pragma unroll
        for (int j = 0; j < 8; ++j) {
            const int n0 = j * 8 + tig * 2;
            float2 bw0 = bw[net * 64 + n0];
            float2 bw1 = bw[net * 64 + n0 + 1];

            uint32_t b0, b1, b2r, b3r, b4, b5, b6, b7;
            ldsm_x4(b0, b1, b2r, b3r, bb + j * (8 * B_ROW_B));        // kt0, kt1
            ldsm_x4(b4, b5, b6, b7,  bb + j * (8 * B_ROW_B) + 64);    // kt2, kt3

            // cA chain starts at b1[n]
            float cA[4] = {bw0.x, bw1.x, bw0.x, bw1.x};
            float cB[4] = {0.f, 0.f, 0.f, 0.f};
            mma16816_v(cA[0], cA[1], cA[2], cA[3],
                       afr[0][0], afr[0][1], afr[0][2], afr[0][3], b0, b1);
            mma16816_v(cB[0], cB[1], cB[2], cB[3],
                       afr[2][0], afr[2][1], afr[2][2], afr[2][3], b4, b5);
            mma16816_v(cA[0], cA[1], cA[2], cA[3],
                       afr[1][0], afr[1][1], afr[1][2], afr[1][3], b2r, b3r);
            mma16816_v(cB[0], cB[1], cB[2], cB[3],
                       afr[3][0], afr[3][1], afr[3][2], afr[3][3], b6, b7);

            float h00 = tanh_fast(cA[0] + cB[0]);
            float h01 = tanh_fast(cA[1] + cB[1]);
            float h10 = tanh_fast(cA[2] + cB[2]);
            float h11 = tanh_fast(cA[3] + cB[3]);
            partial0 = fmaf(h00, bw0.y, fmaf(h01, bw1.y, partial0));
            partial1 = fmaf(h10, bw0.y, fmaf(h11, bw1.y, partial1));
        }
        partial0 += __shfl_xor_sync(0xFFFFFFFFu, partial0, 1);
        partial0 += __shfl_xor_sync(0xFFFFFFFFu, partial0, 2);
        partial1 += __shfl_xor_sync(0xFFFFFFFFu, partial1, 1);
        partial1 += __shfl_xor_sync(0xFFFFFFFFu, partial1, 2);
        const float bbv = b2s[net];
        pv0[nl] = partial0 + bbv;   // row g
        pv1[nl] = partial1 + bbv;   // row g+8
    }

    // ---- shuffle feedback: row rl's value lives in quad (rl&7) ----
    const int src = ((rl & 7) << 2) + tig;
    float a0f = __shfl_sync(0xFFFFFFFFu, pv0[0], src);
    float a1f = __shfl_sync(0xFFFFFFFFu, pv1[0], src);
    float b0f = __shfl_sync(0xFFFFFFFFu, pv0[1], src);
    float b1f = __shfl_sync(0xFFFFFFFFu, pv1[1], src);
    fA = (rl < 8) ? a0f : a1f;
    fB = (rl < 8) ? b0f : b1f;
}

__global__ void __launch_bounds__(256, 2)
nsde_main_kernel(const float* __restrict__ S0g, const float* __restrict__ Kg,
                 const float* __restrict__ Tg,  const float* __restrict__ rfg,
                 const float* __restrict__ Z1g, const float* __restrict__ Z2g,
                 const float* __restrict__ W0g, const float* __restrict__ b0g,
                 const float* __restrict__ W1g, const float* __restrict__ b1g,
                 const float* __restrict__ W2g, const float* __restrict__ b2g)
{
    extern __shared__ char ab[];
    const uint32_t smb = smem_u32(ab);
    const int tid  = threadIdx.x;
    const int warp = tid >> 5;
    const int lane = tid & 31;
    const int rl   = lane & 15;
    const int dup  = lane >> 4;
    const int b    = blockIdx.x & 63;
    const int pb   = blockIdx.x >> 6;

    // ---- stage weights ----
    __half* W1T = (__half*)(ab + OFF_W1T);
    for (int i = tid; i < 4 * 64 * 64; i += 256) {
        const int net = i >> 12;
        const int k   = (i >> 6) & 63;
        const int n   = i & 63;
        W1T[net * 4608 + n * 72 + k] = __float2half_rn(W1g[i]);
    }
    float4* w04 = (float4*)(ab + OFF_W04);
    float2* bw  = (float2*)(ab + OFF_BW);
    float*  b2s = (float*)(ab + OFF_B2);
    float*  red = (float*)(ab + OFF_RED);
    const float rfv = rfg[0];
    {
        const int i = tid;
        const int net = i >> 6, jj = i & 63;
        float4 v;
        v.x = W0g[net * 256 + 0 * 64 + jj];
        v.y = W0g[net * 256 + 1 * 64 + jj];
        v.z = fmaf(W0g[net * 256 + 2 * 64 + jj], rfv, b0g[i]);   // cb in z slot
        v.w = W0g[net * 256 + 3 * 64 + jj];
        w04[i] = v;
        float2 t; t.x = b1g[i]; t.y = W2g[i];
        bw[i] = t;
    }
    if (tid < 4) b2s[tid] = b2g[tid];
    __syncthreads();

    // ---- per-row state ----
    const float S0b = S0g[b], Kb = Kg[b], Tb = Tg[b];
    const float dtv  = Tb * (1.0f / 32.0f);
    const float sqdt = sqrtf(dtv);
    const int   p    = pb * 128 + warp * 16 + rl;
    const float4* z1p = (const float4*)(Z1g + p * NSTEPS);
    const float4* z2p = (const float4*)(Z2g + p * NSTEPS);
    float S = S0b, V = 0.2f;

    for (int jo = 0; jo < 8; ++jo) {
        const float4 z1v = z1p[jo];
        const float4 z2v = z2p[jo];
        #pragma unroll
        for (int ji = 0; ji < 4; ++ji) {
            const int j = jo * 4 + ji;
            const float z1 = (ji == 0) ? z1v.x : (ji == 1) ? z1v.y : (ji == 2) ? z1v.z : z1v.w;
            const float z2 = (ji == 0) ? z2v.x : (ji == 1) ? z2v.y : (ji == 2) ? z2v.z : z2v.w;
            const float tcol = dtv * (float)j;
            float fa, fb;
            run_phase(0, S, V, tcol, ab, smb, warp, lane, rl, dup, fa, fb);
            S = S * (1.0f + fa * dtv + fb * z1);
            run_phase(2, S, V, tcol, ab, smb, warp, lane, rl, dup, fa, fb);
            V = V * (1.0f + fa * dtv + fb * sqdt * z2);
        }
    }

    // ---- payoff + reduction ----
    float pay = (S - Kb < 0.0f) ? 0.0f : S;
    pay += __shfl_xor_sync(0xFFFFFFFFu, pay, 1);
    pay += __shfl_xor_sync(0xFFFFFFFFu, pay, 2);
    pay += __shfl_xor_sync(0xFFFFFFFFu, pay, 4);
    pay += __shfl_xor_sync(0xFFFFFFFFu, pay, 8);
    if (lane == 0) red[warp] = pay;
    __syncthreads();
    if (tid == 0) {
        float s = 0.f;
        #pragma unroll
        for (int w = 0; w < 8; ++w) s += red[w];
        g_partial[blockIdx.x] = s;
    }
}

__global__ void nsde_finalize_kernel(const float* __restrict__ Tg,
                                     const float* __restrict__ rfg,
                                     float* __restrict__ out)
{
    int b = threadIdx.x;
    if (b < 64) {
        float s = (g_partial[b] + g_partial[64 + b]) + (g_partial[128 + b] + g_partial[192 + b]);
        out[b] = __expf(-rfg[0] * Tg[b]) * s * (1.0f / 512.0f);
    }
}

extern "C" void kernel_launch(void* const* d_in, const int* in_sizes, int n_in,
                              void* d_out, int out_size)
{
    const float* S0 = (const float*)d_in[0];
    const float* K  = (const float*)d_in[1];
    const float* T  = (const float*)d_in[2];
    const float* rf = (const float*)d_in[3];
    const float* Z1 = (const float*)d_in[4];
    const float* Z2 = (const float*)d_in[5];
    const float* W0 = (const float*)d_in[6];
    const float* b0 = (const float*)d_in[7];
    const float* W1 = (const float*)d_in[8];
    const float* b1 = (const float*)d_in[9];
    const float* W2 = (const float*)d_in[10];
    const float* b2 = (const float*)d_in[11];
    float* out = (float*)d_out;

    cudaFuncSetAttribute(nsde_main_kernel, cudaFuncAttributeMaxDynamicSharedMemorySize, SMEM_BYTES);
    nsde_main_kernel<<<256, 256, SMEM_BYTES>>>(S0, K, T, rf, Z1, Z2, W0, b0, W1, b1, W2, b2);
    nsde_finalize_kernel<<<1, 64>>>(T, rf, out);
}

// round 15
// speedup vs baseline: 1.0796x; 1.0796x over previous
#include <cuda_runtime.h>
#include <cuda_fp16.h>
#include <cstdint>

#define NSTEPS 32

// ---- smem layout (bytes) ----
#define OFF_W1T 0        // 4 nets x 64 n x 72 halves (pitch 144B) = 36864
#define OFF_A   36864    // 8 warps x 2 nets x 16 rows x 128B (XOR-swizzled) = 32768
#define OFF_W04 69632    // float4[256]  (w.x, w.y, cb, w.w) with cb = w.z*rf + b0
#define OFF_BW  73728    // float2[256] (b1, w2)
#define OFF_F   75776    // 8 warps x 2 nets x 16 floats = 1024
#define OFF_B2  76800    // float[4]
#define OFF_RED 76816    // float[8]
#define SMEM_BYTES 76848

#define A_WARP_B   4096
#define A_NET_B    2048
#define A_PITCH_B  128
#define B_NET_B    9216
#define B_ROW_B    144

__device__ float g_partial[256];

__device__ __forceinline__ uint32_t smem_u32(const void* p) {
    uint32_t a;
    asm("{ .reg .u64 t; cvta.to.shared.u64 t, %1; cvt.u32.u64 %0, t; }" : "=r"(a) : "l"(p));
    return a;
}
__device__ __forceinline__ float tanh_fast(float x) {
    float y;
    asm("tanh.approx.f32 %0, %1;" : "=f"(y) : "f"(x));
    return y;
}
__device__ __forceinline__ void ldsm_x4(uint32_t& r0, uint32_t& r1, uint32_t& r2, uint32_t& r3,
                                        uint32_t addr) {
    asm volatile("ldmatrix.sync.aligned.m8n8.x4.shared.b16 {%0,%1,%2,%3}, [%4];"
        : "=r"(r0), "=r"(r1), "=r"(r2), "=r"(r3) : "r"(addr));
}
__device__ __forceinline__ void mma16816_v(float& c0, float& c1, float& c2, float& c3,
                                           uint32_t a0, uint32_t a1, uint32_t a2, uint32_t a3,
                                           uint32_t b0, uint32_t b1) {
    asm volatile(
        "mma.sync.aligned.m16n8k16.row.col.f32.f16.f16.f32 "
        "{%0,%1,%2,%3},{%4,%5,%6,%7},{%8,%9},{%0,%1,%2,%3};"
        : "+f"(c0), "+f"(c1), "+f"(c2), "+f"(c3)
        : "r"(a0), "r"(a1), "r"(a2), "r"(a3), "r"(b0), "r"(b1));
}

// One phase, fully warp-local. Warp owns 16 rows; lane l = (row l&15, dup l>>4).
__device__ __forceinline__ void run_phase(
    int nb, float S, float V, float tcol,
    char* ab, uint32_t smb, int warp, int lane, int rl, int dup,
    float& fA, float& fB)
{
    const float4* w04 = (const float4*)(ab + OFF_W04);
    const float2* bw  = (const float2*)(ab + OFF_BW);
    const float*  b2s = (const float*)(ab + OFF_B2);
    float* f_w = (float*)(ab + OFF_F) + warp * 32;

    const int g   = lane >> 2;
    const int tig = lane & 3;
    const int jbase = dup * 32;
    const int rsw = rl & 7;

    // ---- layer 0: (wS, wV, cb, wT); 3 FMA + f32 tanh per unit ----
    {
        char* Abase = ab + OFF_A + warp * A_WARP_B + rl * A_PITCH_B;
        #pragma unroll
        for (int nl = 0; nl < 2; ++nl) {
            const int net = nb + nl;
            const float4* wp = w04 + net * 64 + jbase;
            char* An = Abase + nl * A_NET_B;
            #pragma unroll
            for (int jj = 0; jj < 32; jj += 4) {
                float4 w0 = wp[jj], w1 = wp[jj + 1], w2 = wp[jj + 2], w3 = wp[jj + 3];
                float p0 = fmaf(w0.x, S, fmaf(w0.y, V, fmaf(w0.w, tcol, w0.z)));
                float p1 = fmaf(w1.x, S, fmaf(w1.y, V, fmaf(w1.w, tcol, w1.z)));
                float p2 = fmaf(w2.x, S, fmaf(w2.y, V, fmaf(w2.w, tcol, w2.z)));
                float p3 = fmaf(w3.x, S, fmaf(w3.y, V, fmaf(w3.w, tcol, w3.z)));
                __half2 ha = __floats2half2_rn(tanh_fast(p0), tanh_fast(p1));
                __half2 hb = __floats2half2_rn(tanh_fast(p2), tanh_fast(p3));
                uint2 pk;
                pk.x = *(const uint32_t*)&ha;
                pk.y = *(const uint32_t*)&hb;
                const int unit = (dup * 4 + (jj >> 3)) ^ rsw;
                *(uint2*)(An + unit * 16 + ((jj >> 2) & 1) * 8) = pk;
            }
        }
    }
    __syncwarp();

    // ---- layer 1 + epilogue, per net ----
    const int arow = (lane & 7) + ((lane >> 3) & 1) * 8;
    const int akh  = (lane >> 4) & 1;
    const int asw  = arow & 7;
    const uint32_t a_lane = smb + OFF_A + warp * A_WARP_B + arow * A_PITCH_B;
    const uint32_t b_lane = smb + OFF_W1T + (lane & 7) * B_ROW_B + (lane >> 3) * 16;

    #pragma unroll
    for (int nl = 0; nl < 2; ++nl) {
        const int net = nb + nl;

        uint32_t afr[4][4];
        {
            const uint32_t abase = a_lane + nl * A_NET_B;
            #pragma unroll
            for (int kt = 0; kt < 4; ++kt) {
                const int unit = (kt * 2 + akh) ^ asw;
                ldsm_x4(afr[kt][0], afr[kt][1], afr[kt][2], afr[kt][3],
                        abase + unit * 16);
            }
        }

        float partial0 = 0.f, partial1 = 0.f;
        const uint32_t bb = b_lane + net * B_NET_B;

        #pragma unroll
        for (int j = 0; j < 8; ++j) {
            const int n0 = j * 8 + tig * 2;
            float2 bw0 = bw[net * 64 + n0];
            float2 bw1 = bw[net * 64 + n0 + 1];

            uint32_t b0, b1, b2r, b3r, b4, b5, b6, b7;
            ldsm_x4(b0, b1, b2r, b3r, bb + j * (8 * B_ROW_B));        // kt0, kt1
            ldsm_x4(b4, b5, b6, b7,  bb + j * (8 * B_ROW_B) + 64);    // kt2, kt3

            // cA chain starts at b1[n]
            float cA[4] = {bw0.x, bw1.x, bw0.x, bw1.x};
            float cB[4] = {0.f, 0.f, 0.f, 0.f};
            mma16816_v(cA[0], cA[1], cA[2], cA[3],
                       afr[0][0], afr[0][1], afr[0][2], afr[0][3], b0, b1);
            mma16816_v(cB[0], cB[1], cB[2], cB[3],
                       afr[2][0], afr[2][1], afr[2][2], afr[2][3], b4, b5);
            mma16816_v(cA[0], cA[1], cA[2], cA[3],
                       afr[1][0], afr[1][1], afr[1][2], afr[1][3], b2r, b3r);
            mma16816_v(cB[0], cB[1], cB[2], cB[3],
                       afr[3][0], afr[3][1], afr[3][2], afr[3][3], b6, b7);

            float h00 = tanh_fast(cA[0] + cB[0]);
            float h01 = tanh_fast(cA[1] + cB[1]);
            float h10 = tanh_fast(cA[2] + cB[2]);
            float h11 = tanh_fast(cA[3] + cB[3]);
            partial0 = fmaf(h00, bw0.y, fmaf(h01, bw1.y, partial0));
            partial1 = fmaf(h10, bw0.y, fmaf(h11, bw1.y, partial1));
        }
        partial0 += __shfl_xor_sync(0xFFFFFFFFu, partial0, 1);
        partial0 += __shfl_xor_sync(0xFFFFFFFFu, partial0, 2);
        partial1 += __shfl_xor_sync(0xFFFFFFFFu, partial1, 1);
        partial1 += __shfl_xor_sync(0xFFFFFFFFu, partial1, 2);
        if (tig == 0) {
            const float bbv = b2s[net];
            f_w[nl * 16 + g]     = partial0 + bbv;
            f_w[nl * 16 + g + 8] = partial1 + bbv;
        }
    }
    __syncwarp();
    fA = f_w[rl];
    fB = f_w[16 + rl];
}

__global__ void __launch_bounds__(256, 2)
nsde_main_kernel(const float* __restrict__ S0g, const float* __restrict__ Kg,
                 const float* __restrict__ Tg,  const float* __restrict__ rfg,
                 const float* __restrict__ Z1g, const float* __restrict__ Z2g,
                 const float* __restrict__ W0g, const float* __restrict__ b0g,
                 const float* __restrict__ W1g, const float* __restrict__ b1g,
                 const float* __restrict__ W2g, const float* __restrict__ b2g)
{
    extern __shared__ char ab[];
    const uint32_t smb = smem_u32(ab);
    const int tid  = threadIdx.x;
    const int warp = tid >> 5;
    const int lane = tid & 31;
    const int rl   = lane & 15;
    const int dup  = lane >> 4;
    const int b    = blockIdx.x & 63;
    const int pb   = blockIdx.x >> 6;

    // ---- stage weights ----
    __half* W1T = (__half*)(ab + OFF_W1T);
    for (int i = tid; i < 4 * 64 * 64; i += 256) {
        const int net = i >> 12;
        const int k   = (i >> 6) & 63;
        const int n   = i & 63;
        W1T[net * 4608 + n * 72 + k] = __float2half_rn(W1g[i]);
    }
    float4* w04 = (float4*)(ab + OFF_W04);
    float2* bw  = (float2*)(ab + OFF_BW);
    float*  b2s = (float*)(ab + OFF_B2);
    float*  red = (float*)(ab + OFF_RED);
    const float rfv = rfg[0];
    {
        const int i = tid;
        const int net = i >> 6, jj = i & 63;
        float4 v;
        v.x = W0g[net * 256 + 0 * 64 + jj];
        v.y = W0g[net * 256 + 1 * 64 + jj];
        v.z = fmaf(W0g[net * 256 + 2 * 64 + jj], rfv, b0g[i]);   // cb in z slot
        v.w = W0g[net * 256 + 3 * 64 + jj];
        w04[i] = v;
        float2 t; t.x = b1g[i]; t.y = W2g[i];
        bw[i] = t;
    }
    if (tid < 4) b2s[tid] = b2g[tid];
    __syncthreads();

    // ---- per-row state ----
    const float S0b = S0g[b], Kb = Kg[b], Tb = Tg[b];
    const float dtv  = Tb * (1.0f / 32.0f);
    const float sqdt = sqrtf(dtv);
    const int   p    = pb * 128 + warp * 16 + rl;
    const float4* z1p = (const float4*)(Z1g + p * NSTEPS);
    const float4* z2p = (const float4*)(Z2g + p * NSTEPS);
    float S = S0b, V = 0.2f;

    for (int jo = 0; jo < 8; ++jo) {
        const float4 z1v = z1p[jo];
        const float4 z2v = z2p[jo];
        #pragma unroll
        for (int ji = 0; ji < 4; ++ji) {
            const int j = jo * 4 + ji;
            const float z1 = (ji == 0) ? z1v.x : (ji == 1) ? z1v.y : (ji == 2) ? z1v.z : z1v.w;
            const float z2 = (ji == 0) ? z2v.x : (ji == 1) ? z2v.y : (ji == 2) ? z2v.z : z2v.w;
            const float tcol = dtv * (float)j;
            float fa, fb;
            run_phase(0, S, V, tcol, ab, smb, warp, lane, rl, dup, fa, fb);
            S = S * (1.0f + fa * dtv + fb * z1);
            run_phase(2, S, V, tcol, ab, smb, warp, lane, rl, dup, fa, fb);
            V = V * (1.0f + fa * dtv + fb * sqdt * z2);
        }
    }

    // ---- payoff + reduction ----
    float pay = (S - Kb < 0.0f) ? 0.0f : S;
    pay += __shfl_xor_sync(0xFFFFFFFFu, pay, 1);
    pay += __shfl_xor_sync(0xFFFFFFFFu, pay, 2);
    pay += __shfl_xor_sync(0xFFFFFFFFu, pay, 4);
    pay += __shfl_xor_sync(0xFFFFFFFFu, pay, 8);
    if (lane == 0) red[warp] = pay;
    __syncthreads();
    if (tid == 0) {
        float s = 0.f;
        #pragma unroll
        for (int w = 0; w < 8; ++w) s += red[w];
        g_partial[blockIdx.x] = s;
    }
}

__global__ void nsde_finalize_kernel(const float* __restrict__ Tg,
                                     const float* __restrict__ rfg,
                                     float* __restrict__ out)
{
    int b = threadIdx.x;
    if (b < 64) {
        float s = (g_partial[b] + g_partial[64 + b]) + (g_partial[128 + b] + g_partial[192 + b]);
        out[b] = __expf(-rfg[0] * Tg[b]) * s * (1.0f / 512.0f);
    }
}

extern "C" void kernel_launch(void* const* d_in, const int* in_sizes, int n_in,
                              void* d_out, int out_size)
{
    const float* S0 = (const float*)d_in[0];
    const float* K  = (const float*)d_in[1];
    const float* T  = (const float*)d_in[2];
    const float* rf = (const float*)d_in[3];
    const float* Z1 = (const float*)d_in[4];
    const float* Z2 = (const float*)d_in[5];
    const float* W0 = (const float*)d_in[6];
    const float* b0 = (const float*)d_in[7];
    const float* W1 = (const float*)d_in[8];
    const float* b1 = (const float*)d_in[9];
    const float* W2 = (const float*)d_in[10];
    const float* b2 = (const float*)d_in[11];
    float* out = (float*)d_out;

    cudaFuncSetAttribute(nsde_main_kernel, cudaFuncAttributeMaxDynamicSharedMemorySize, SMEM_BYTES);
    nsde_main_kernel<<<256, 256, SMEM_BYTES>>>(S0, K, T, rf, Z1, Z2, W0, b0, W1, b1, W2, b2);
    nsde_finalize_kernel<<<1, 64>>>(T, rf, out);
}

// round 16
// speedup vs baseline: 1.2234x; 1.1332x over previous
#include <cuda_runtime.h>
#include <cuda_fp16.h>
#include <cstdint>

#define NSTEPS 32

// ---- smem layout (bytes) ----
#define OFF_W1T 0        // 4 nets x 64 n x 72 halves (pitch 144B) = 36864
#define OFF_W04 36864    // float4[256]  (w.x, w.y, cb, w.w) with cb = w.z*rf + b0
#define OFF_BW  40960    // float2[256] (b1, w2)
#define OFF_F   43008    // 8 warps x 2 nets x 16 floats = 1024
#define OFF_B2  44032    // float[4]
#define OFF_RED 44048    // float[8]
#define SMEM_BYTES 44080

#define B_NET_B    9216
#define B_ROW_B    144

__device__ float g_partial[256];

__device__ __forceinline__ uint32_t smem_u32(const void* p) {
    uint32_t a;
    asm("{ .reg .u64 t; cvta.to.shared.u64 t, %1; cvt.u32.u64 %0, t; }" : "=r"(a) : "l"(p));
    return a;
}
__device__ __forceinline__ float tanh_fast(float x) {
    float y;
    asm("tanh.approx.f32 %0, %1;" : "=f"(y) : "f"(x));
    return y;
}
__device__ __forceinline__ void ldsm_x4(uint32_t& r0, uint32_t& r1, uint32_t& r2, uint32_t& r3,
                                        uint32_t addr) {
    asm volatile("ldmatrix.sync.aligned.m8n8.x4.shared.b16 {%0,%1,%2,%3}, [%4];"
        : "=r"(r0), "=r"(r1), "=r"(r2), "=r"(r3) : "r"(addr));
}
__device__ __forceinline__ void mma16816_v(float& c0, float& c1, float& c2, float& c3,
                                           uint32_t a0, uint32_t a1, uint32_t a2, uint32_t a3,
                                           uint32_t b0, uint32_t b1) {
    asm volatile(
        "mma.sync.aligned.m16n8k16.row.col.f32.f16.f16.f32 "
        "{%0,%1,%2,%3},{%4,%5,%6,%7},{%8,%9},{%0,%1,%2,%3};"
        : "+f"(c0), "+f"(c1), "+f"(c2), "+f"(c3)
        : "r"(a0), "r"(a1), "r"(a2), "r"(a3), "r"(b0), "r"(b1));
}

// One phase, fully warp-local. Lane l = (row l&15, dup l>>4) for state;
// A-fragments computed DIRECTLY in registers (no smem A tile, no ldsm-A).
__device__ __forceinline__ void run_phase(
    int nb, float S, float V, float tcol,
    char* ab, uint32_t smb, int warp, int lane, int rl,
    float& fA, float& fB)
{
    const float4* w04 = (const float4*)(ab + OFF_W04);
    const float2* bw  = (const float2*)(ab + OFF_BW);
    const float*  b2s = (const float*)(ab + OFF_B2);
    float* f_w = (float*)(ab + OFF_F) + warp * 32;

    const int g   = lane >> 2;
    const int tig = lane & 3;

    __syncwarp();   // order prior phase's f reads before this phase's f writes

    // fragment rows for this lane: g and g+8 — broadcast their (S, V)
    const float Sg = __shfl_sync(0xFFFFFFFFu, S, g);
    const float Vg = __shfl_sync(0xFFFFFFFFu, V, g);
    const float S8 = __shfl_sync(0xFFFFFFFFu, S, g + 8);
    const float V8 = __shfl_sync(0xFFFFFFFFu, V, g + 8);

    const uint32_t b_lane = smb + OFF_W1T + (lane & 7) * B_ROW_B + (lane >> 3) * 16;

    #pragma unroll
    for (int nl = 0; nl < 2; ++nl) {
        const int net = nb + nl;
        const float4* wp = w04 + net * 64;

        // ---- layer 0 directly into A-fragment registers ----
        // afr[kt][0]=row g k{2tig,2tig+1}, [1]=row g+8 same k, [2]/[3]=+8 k-offset
        uint32_t afr[4][4];
        #pragma unroll
        for (int kt = 0; kt < 4; ++kt) {
            #pragma unroll
            for (int d = 0; d < 2; ++d) {
                const int k0 = kt * 16 + tig * 2 + d * 8;
                float4 wa = wp[k0];
                float4 wbv = wp[k0 + 1];
                float ca = fmaf(wa.w,  tcol, wa.z);
                float cb = fmaf(wbv.w, tcol, wbv.z);
                __half2 hg = __floats2half2_rn(
                    tanh_fast(fmaf(wa.x,  Sg, fmaf(wa.y,  Vg, ca))),
                    tanh_fast(fmaf(wbv.x, Sg, fmaf(wbv.y, Vg, cb))));
                __half2 h8 = __floats2half2_rn(
                    tanh_fast(fmaf(wa.x,  S8, fmaf(wa.y,  V8, ca))),
                    tanh_fast(fmaf(wbv.x, S8, fmaf(wbv.y, V8, cb))));
                afr[kt][d * 2]     = *(const uint32_t*)&hg;
                afr[kt][d * 2 + 1] = *(const uint32_t*)&h8;
            }
        }

        // ---- layer 1 + epilogue ----
        float partial0 = 0.f, partial1 = 0.f;
        const uint32_t bb = b_lane + net * B_NET_B;

        #pragma unroll
        for (int j = 0; j < 8; ++j) {
            const int n0 = j * 8 + tig * 2;
            float2 bw0 = bw[net * 64 + n0];
            float2 bw1 = bw[net * 64 + n0 + 1];

            uint32_t b0, b1, b2r, b3r, b4, b5, b6, b7;
            ldsm_x4(b0, b1, b2r, b3r, bb + j * (8 * B_ROW_B));        // kt0, kt1
            ldsm_x4(b4, b5, b6, b7,  bb + j * (8 * B_ROW_B) + 64);    // kt2, kt3

            float cA[4] = {bw0.x, bw1.x, bw0.x, bw1.x};   // start at b1[n]
            float cB[4] = {0.f, 0.f, 0.f, 0.f};
            mma16816_v(cA[0], cA[1], cA[2], cA[3],
                       afr[0][0], afr[0][1], afr[0][2], afr[0][3], b0, b1);
            mma16816_v(cB[0], cB[1], cB[2], cB[3],
                       afr[2][0], afr[2][1], afr[2][2], afr[2][3], b4, b5);
            mma16816_v(cA[0], cA[1], cA[2], cA[3],
                       afr[1][0], afr[1][1], afr[1][2], afr[1][3], b2r, b3r);
            mma16816_v(cB[0], cB[1], cB[2], cB[3],
                       afr[3][0], afr[3][1], afr[3][2], afr[3][3], b6, b7);

            float h00 = tanh_fast(cA[0] + cB[0]);
            float h01 = tanh_fast(cA[1] + cB[1]);
            float h10 = tanh_fast(cA[2] + cB[2]);
            float h11 = tanh_fast(cA[3] + cB[3]);
            partial0 = fmaf(h00, bw0.y, fmaf(h01, bw1.y, partial0));
            partial1 = fmaf(h10, bw0.y, fmaf(h11, bw1.y, partial1));
        }
        partial0 += __shfl_xor_sync(0xFFFFFFFFu, partial0, 1);
        partial0 += __shfl_xor_sync(0xFFFFFFFFu, partial0, 2);
        partial1 += __shfl_xor_sync(0xFFFFFFFFu, partial1, 1);
        partial1 += __shfl_xor_sync(0xFFFFFFFFu, partial1, 2);
        if (tig == 0) {
            const float bbv = b2s[net];
            f_w[nl * 16 + g]     = partial0 + bbv;
            f_w[nl * 16 + g + 8] = partial1 + bbv;
        }
    }
    __syncwarp();
    fA = f_w[rl];
    fB = f_w[16 + rl];
}

__global__ void __launch_bounds__(256, 2)
nsde_main_kernel(const float* __restrict__ S0g, const float* __restrict__ Kg,
                 const float* __restrict__ Tg,  const float* __restrict__ rfg,
                 const float* __restrict__ Z1g, const float* __restrict__ Z2g,
                 const float* __restrict__ W0g, const float* __restrict__ b0g,
                 const float* __restrict__ W1g, const float* __restrict__ b1g,
                 const float* __restrict__ W2g, const float* __restrict__ b2g)
{
    extern __shared__ char ab[];
    const uint32_t smb = smem_u32(ab);
    const int tid  = threadIdx.x;
    const int warp = tid >> 5;
    const int lane = tid & 31;
    const int rl   = lane & 15;
    const int b    = blockIdx.x & 63;
    const int pb   = blockIdx.x >> 6;

    // ---- stage weights ----
    __half* W1T = (__half*)(ab + OFF_W1T);
    for (int i = tid; i < 4 * 64 * 64; i += 256) {
        const int net = i >> 12;
        const int k   = (i >> 6) & 63;
        const int n   = i & 63;
        W1T[net * 4608 + n * 72 + k] = __float2half_rn(W1g[i]);
    }
    float4* w04 = (float4*)(ab + OFF_W04);
    float2* bw  = (float2*)(ab + OFF_BW);
    float*  b2s = (float*)(ab + OFF_B2);
    float*  red = (float*)(ab + OFF_RED);
    const float rfv = rfg[0];
    {
        const int i = tid;
        const int net = i >> 6, jj = i & 63;
        float4 v;
        v.x = W0g[net * 256 + 0 * 64 + jj];
        v.y = W0g[net * 256 + 1 * 64 + jj];
        v.z = fmaf(W0g[net * 256 + 2 * 64 + jj], rfv, b0g[i]);   // cb in z slot
        v.w = W0g[net * 256 + 3 * 64 + jj];
        w04[i] = v;
        float2 t; t.x = b1g[i]; t.y = W2g[i];
        bw[i] = t;
    }
    if (tid < 4) b2s[tid] = b2g[tid];
    __syncthreads();

    // ---- per-row state (row = warp*16 + rl, duplicated across lane>>4) ----
    const float S0b = S0g[b], Kb = Kg[b], Tb = Tg[b];
    const float dtv  = Tb * (1.0f / 32.0f);
    const float sqdt = sqrtf(dtv);
    const int   p    = pb * 128 + warp * 16 + rl;
    const float4* z1p = (const float4*)(Z1g + p * NSTEPS);
    const float4* z2p = (const float4*)(Z2g + p * NSTEPS);
    float S = S0b, V = 0.2f;

    for (int jo = 0; jo < 8; ++jo) {
        const float4 z1v = z1p[jo];
        const float4 z2v = z2p[jo];
        #pragma unroll
        for (int ji = 0; ji < 4; ++ji) {
            const int j = jo * 4 + ji;
            const float z1 = (ji == 0) ? z1v.x : (ji == 1) ? z1v.y : (ji == 2) ? z1v.z : z1v.w;
            const float z2 = (ji == 0) ? z2v.x : (ji == 1) ? z2v.y : (ji == 2) ? z2v.z : z2v.w;
            const float tcol = dtv * (float)j;
            float fa, fb;
            run_phase(0, S, V, tcol, ab, smb, warp, lane, rl, fa, fb);
            S = S * (1.0f + fa * dtv + fb * z1);
            run_phase(2, S, V, tcol, ab, smb, warp, lane, rl, fa, fb);
            V = V * (1.0f + fa * dtv + fb * sqdt * z2);
        }
    }

    // ---- payoff + reduction ----
    float pay = (S - Kb < 0.0f) ? 0.0f : S;
    pay += __shfl_xor_sync(0xFFFFFFFFu, pay, 1);
    pay += __shfl_xor_sync(0xFFFFFFFFu, pay, 2);
    pay += __shfl_xor_sync(0xFFFFFFFFu, pay, 4);
    pay += __shfl_xor_sync(0xFFFFFFFFu, pay, 8);
    if (lane == 0) red[warp] = pay;
    __syncthreads();
    if (tid == 0) {
        float s = 0.f;
        #pragma unroll
        for (int w = 0; w < 8; ++w) s += red[w];
        g_partial[blockIdx.x] = s;
    }
}

__global__ void nsde_finalize_kernel(const float* __restrict__ Tg,
                                     const float* __restrict__ rfg,
                                     float* __restrict__ out)
{
    int b = threadIdx.x;
    if (b < 64) {
        float s = (g_partial[b] + g_partial[64 + b]) + (g_partial[128 + b] + g_partial[192 + b]);
        out[b] = __expf(-rfg[0] * Tg[b]) * s * (1.0f / 512.0f);
    }
}

extern "C" void kernel_launch(void* const* d_in, const int* in_sizes, int n_in,
                              void* d_out, int out_size)
{
    const float* S0 = (const float*)d_in[0];
    const float* K  = (const float*)d_in[1];
    const float* T  = (const float*)d_in[2];
    const float* rf = (const float*)d_in[3];
    const float* Z1 = (const float*)d_in[4];
    const float* Z2 = (const float*)d_in[5];
    const float* W0 = (const float*)d_in[6];
    const float* b0 = (const float*)d_in[7];
    const float* W1 = (const float*)d_in[8];
    const float* b1 = (const float*)d_in[9];
    const float* W2 = (const float*)d_in[10];
    const float* b2 = (const float*)d_in[11];
    float* out = (float*)d_out;

    cudaFuncSetAttribute(nsde_main_kernel, cudaFuncAttributeMaxDynamicSharedMemorySize, SMEM_BYTES);
    nsde_main_kernel<<<256, 256, SMEM_BYTES>>>(S0, K, T, rf, Z1, Z2, W0, b0, W1, b1, W2, b2);
    nsde_finalize_kernel<<<1, 64>>>(T, rf, out);
}